// round 3
// baseline (speedup 1.0000x reference)
#include <cuda_runtime.h>

#define TN (1 << 20)
#define LOG2TN 20
#define KM 3
#define C_ALPHA 2000.0f
#define C_TAU 1e-7f
#define C_TAU2 1e-14f
#define PI_D 3.14159265358979323846

// ---------------- scratch (device globals; no allocation allowed) ----------------
__device__ float2 g_A[3 * TN];       // FFT ping buffer
__device__ float2 g_Bb[3 * TN];      // FFT pong buffer (fhat after fwd; inv stage-0 out)
__device__ float2 g_lamPrev[TN];     // lambda stash for convergence diff
__device__ double g_accM[8];         // monotone accumulators
__device__ unsigned int g_ctr;       // barrier arrival counter (monotone)
__device__ float  g_om[KM];

// ---------------- complex helpers ----------------
__device__ __forceinline__ float2 cadd(float2 a, float2 b) { return make_float2(a.x + b.x, a.y + b.y); }
__device__ __forceinline__ float2 csub(float2 a, float2 b) { return make_float2(a.x - b.x, a.y - b.y); }
__device__ __forceinline__ float2 cmul(float2 a, float2 b) {
    return make_float2(a.x * b.x - a.y * b.y, a.x * b.y + a.y * b.x);
}

__global__ void init_kernel(const float* __restrict__ om0) {
    int t = threadIdx.x;
    if (t < KM) g_om[t] = 0.5f * om0[t];
    if (t < 8) g_accM[t] = 0.0;
    if (t == 0) g_ctr = 0u;
}

// ---------------- radix-16 butterfly (4x4 four-step, constant twiddles) ----------------
template <bool FWD>
__device__ __forceinline__ void bf4(float2 a, float2 b, float2 c, float2 d,
                                    float2& o0, float2& o1, float2& o2, float2& o3) {
    float2 apc = cadd(a, c), amc = csub(a, c);
    float2 bpd = cadd(b, d), bmd = csub(b, d);
    o0 = cadd(apc, bpd);
    o2 = csub(apc, bpd);
    if (FWD) {  // w4 = -i
        o1 = make_float2(amc.x + bmd.y, amc.y - bmd.x);
        o3 = make_float2(amc.x - bmd.y, amc.y + bmd.x);
    } else {    // w4 = +i
        o1 = make_float2(amc.x - bmd.y, amc.y + bmd.x);
        o3 = make_float2(amc.x + bmd.y, amc.y - bmd.x);
    }
}

template <bool FWD>
__device__ __forceinline__ void fft16(float2* z) {
    const float S  = FWD ? -1.f : 1.f;
    const float C1 = 0.92387953251128674f;   // cos(pi/8)
    const float S1 = 0.38268343236508977f;   // sin(pi/8)
    const float R  = 0.70710678118654752f;   // sqrt(2)/2
    float2 A[16];
#pragma unroll
    for (int n1 = 0; n1 < 4; n1++)
        bf4<FWD>(z[n1], z[n1 + 4], z[n1 + 8], z[n1 + 12],
                 A[n1 * 4 + 0], A[n1 * 4 + 1], A[n1 * 4 + 2], A[n1 * 4 + 3]);
    A[5]  = cmul(A[5],  make_float2( C1,  S * S1));
    A[6]  = cmul(A[6],  make_float2( R,   S * R ));
    A[7]  = cmul(A[7],  make_float2( S1,  S * C1));
    A[9]  = cmul(A[9],  make_float2( R,   S * R ));
    A[10] = make_float2(-S * A[10].y, S * A[10].x);
    A[11] = cmul(A[11], make_float2(-R,   S * R ));
    A[13] = cmul(A[13], make_float2( S1,  S * C1));
    A[14] = cmul(A[14], make_float2(-R,   S * R ));
    A[15] = cmul(A[15], make_float2(-C1, -S * S1));
#pragma unroll
    for (int k2 = 0; k2 < 4; k2++)
        bf4<FWD>(A[k2], A[4 + k2], A[8 + k2], A[12 + k2],
                 z[k2], z[k2 + 4], z[k2 + 8], z[k2 + 12]);
}

// ---------------- forward stage 0 fused with (-1)^n pack ----------------
__global__ void __launch_bounds__(256) fwd0_kernel(const float* __restrict__ x) {
    int p = blockIdx.x * blockDim.x + threadIdx.x;  // 0..65535
    float sgn = (p & 1) ? -1.f : 1.f;
    float2 z[16];
#pragma unroll
    for (int j = 0; j < 16; j++) z[j] = make_float2(sgn * x[p + j * 65536], 0.f);
    fft16<true>(z);
    float th0 = (float)(-2.0 * PI_D / (double)TN);
    float sn, cs;
    sincosf(th0 * (float)p, &sn, &cs);
    float2 w = make_float2(cs, sn), cur = w;
    float2* __restrict__ Y = g_Bb;
    int ob = p << 4;
    Y[ob] = z[0];
#pragma unroll
    for (int r = 1; r < 16; r++) {
        Y[ob + r] = cmul(z[r], cur);
        cur = cmul(cur, w);
    }
}

// ---------------- generic radix-16 Stockham stage (batched) ----------------
template <bool FWD>
__global__ void __launch_bounds__(256) fft16_stage(int inIsB, int log2s, float th0) {
    int gid  = blockIdx.x * blockDim.x + threadIdx.x;
    int tid  = gid & 65535;
    int base = (gid >> 16) << LOG2TN;
    const float2* __restrict__ X = (inIsB ? g_Bb : g_A) + base;
    float2* __restrict__       Y = (inIsB ? g_A : g_Bb) + base;
    int s_ = 1 << log2s;
    int q  = tid & (s_ - 1);
    int p  = tid >> log2s;
    int m  = TN >> (log2s + 4);

    float2 z[16];
#pragma unroll
    for (int j = 0; j < 16; j++) z[j] = X[q + ((p + j * m) << log2s)];
    fft16<FWD>(z);
    float sn, cs;
    sincosf(th0 * (float)p, &sn, &cs);
    float2 w = make_float2(cs, sn), cur = w;
    int ob = q + ((p << 4) << log2s);
    Y[ob] = z[0];
#pragma unroll
    for (int r = 1; r < 16; r++) {
        Y[ob + (r << log2s)] = cmul(z[r], cur);
        cur = cmul(cur, w);
    }
}

// ---------------- final inverse stage fused with real output ----------------
// i=4: s=65536, p=0 (no twiddle). out[k*TN + q + r*65536] = Re(z[r]) * (-1)^q / TN
__global__ void __launch_bounds__(256) inv_final_kernel(float* __restrict__ out) {
    int gid = blockIdx.x * blockDim.x + threadIdx.x;
    int q = gid & 65535;
    int b = gid >> 16;
    const float2* __restrict__ X = g_A + (b << LOG2TN);
    float2 z[16];
#pragma unroll
    for (int j = 0; j < 16; j++) z[j] = X[q + (j << 16)];
    fft16<false>(z);
    float sg = (q & 1) ? -(1.0f / 1048576.0f) : (1.0f / 1048576.0f);
    float* __restrict__ o = out + (b << LOG2TN);
#pragma unroll
    for (int r = 0; r < 16; r++) o[q + (r << 16)] = z[r].x * sg;
}

// ---------------- persistent VMD iteration kernel ----------------
#define NBP 256
#define NTP 256
#define EP 16     // NBP*NTP*EP = 2^20

__global__ void __launch_bounds__(NTP, 2) vmd_persist() {
    int tid = threadIdx.x;
    int gid = blockIdx.x * NTP + tid;

    float fhx[EP], fhy[EP], lax[EP], lay[EP];
#pragma unroll
    for (int e = 0; e < EP; e++) {
        float2 v = g_Bb[e * 65536 + gid];
        fhx[e] = v.x; fhy[e] = v.y;
        lax[e] = 0.f; lay[e] = 0.f;
    }
    float om0 = g_om[0], om1 = g_om[1], om2 = g_om[2];
    float oD0 = om0, oD1 = om1, oD2 = om2;

    __shared__ float  sred[8][NTP / 32];
    __shared__ double sPrev[8];
    __shared__ float  sOm[3];
    __shared__ int    sTerm;
    if (tid < 8) sPrev[tid] = 0.0;
    __syncthreads();

    const float FRC = 1.0f / 1048576.0f;

    for (int n = 0; n < 50; n++) {
        float a0 = 0.f, a1 = 0.f, a2 = 0.f, a3 = 0.f, a4 = 0.f, a5 = 0.f, a6 = 0.f, a7 = 0.f;
        bool doDiff  = (n > 0) && (n % 10 == 0);
        bool doStash = (n % 10 == 9) && (n < 49);

#pragma unroll
        for (int e = 0; e < EP; e++) {
            int t = e * 65536 + gid;
            float fr = fmaf((float)gid, FRC, (float)(e * 65536) * FRC - 0.5f);
            float d0 = fr - om0; d0 *= d0;
            float d1 = fr - om1; d1 *= d1;
            float d2 = fr - om2; d2 *= d2;
            float g0 = 1.0f / (1.0f + C_ALPHA * ((d0 + C_TAU2) + d1));
            float g1 = 1.0f / (1.0f + C_ALPHA * (((d1 + C_TAU2) + d0) + d2));
            float g2 = 1.0f / (1.0f + C_ALPHA * ((d2 + C_TAU2) + d1));
            float nr = fhx[e] - 0.5f * lax[e];
            float ni = fhy[e] - 0.5f * lay[e];
            float m2 = nr * nr + ni * ni;
            float p0 = m2 * g0 * g0;
            float p1 = m2 * g1 * g1;
            float p2 = m2 * g2 * g2;
            a0 += p0; a1 += p1; a2 += p2;
            a3 += p0 * fr; a4 += p1 * fr; a5 += p2 * fr;

            if (doDiff) {
                float2 lp = g_lamPrev[t];
                float q0 = fr - oD0; q0 *= q0;
                float q1 = fr - oD1; q1 *= q1;
                float q2 = fr - oD2; q2 *= q2;
                float h0 = 1.0f / (1.0f + C_ALPHA * ((q0 + C_TAU2) + q1));
                float h1 = 1.0f / (1.0f + C_ALPHA * (((q1 + C_TAU2) + q0) + q2));
                float h2 = 1.0f / (1.0f + C_ALPHA * ((q2 + C_TAU2) + q1));
                float mr = fhx[e] - 0.5f * lp.x;
                float mi = fhy[e] - 0.5f * lp.y;
                float ex0 = nr * g0 - mr * h0, ey0 = ni * g0 - mi * h0;
                float ex1 = nr * g1 - mr * h1, ey1 = ni * g1 - mi * h1;
                float ex2 = nr * g2 - mr * h2, ey2 = ni * g2 - mi * h2;
                a6 += ex0 * ex0 + ey0 * ey0 + ex1 * ex1 + ey1 * ey1 + ex2 * ex2 + ey2 * ey2;
                a7 += (mr * mr + mi * mi) * (h0 * h0 + h1 * h1 + h2 * h2);
            }
            if (doStash) g_lamPrev[t] = make_float2(lax[e], lay[e]);

            float G = g0 + g1 + g2;
            lax[e] = lax[e] + C_TAU * (nr * G - fhx[e]);
            lay[e] = lay[e] + C_TAU * (ni * G - fhy[e]);
        }

        // ---- block reduce 8 accumulators ----
        float vals[8] = {a0, a1, a2, a3, a4, a5, a6, a7};
#pragma unroll
        for (int i = 0; i < 8; i++) {
            float v = vals[i];
#pragma unroll
            for (int o = 16; o > 0; o >>= 1) v += __shfl_down_sync(0xffffffffu, v, o);
            vals[i] = v;
        }
        int wid = tid >> 5, lid = tid & 31;
        if (lid == 0) {
#pragma unroll
            for (int i = 0; i < 8; i++) sred[i][wid] = vals[i];
        }
        __syncthreads();
        if (tid < 8) {
            double s = 0.0;
#pragma unroll
            for (int w = 0; w < NTP / 32; w++) s += (double)sred[tid][w];
            atomicAdd(&g_accM[tid], s);
            __threadfence();
        }
        __syncthreads();

        // ---- grid barrier (tight spin) + redundant scalar update ----
        if (tid == 0) {
            atomicAdd(&g_ctr, 1u);
            unsigned target = (unsigned)NBP * (unsigned)(n + 1);
            const volatile unsigned* vc = (const volatile unsigned*)&g_ctr;
            while (*vc < target) { }
            __threadfence();
            double T[8], it[8];
#pragma unroll
            for (int i = 0; i < 8; i++) {
                T[i]  = *((const volatile double*)&g_accM[i]);
                it[i] = T[i] - sPrev[i];
                sPrev[i] = T[i];
            }
            float on0 = (float)(it[3] / (it[0] + 1e-8));
            float on1 = (float)(it[4] / (it[1] + 1e-8));
            float on2 = (float)(it[5] / (it[2] + 1e-8));
            float odiff = (fabsf(on0 - on2) + fabsf(on1 - on0) + fabsf(on2 - on1)) * (1.0f / 3.0f);
            double udiff = (n == 0) ? (it[0] + it[1] + it[2]) / 1e-8
                                    : it[6] / (it[7] + 1e-8);
            int done = (n % 10 == 0) && (udiff < 1e-6) && (odiff < 1e-6f);
            sOm[0] = on0; sOm[1] = on1; sOm[2] = on2;
            sTerm = (done || n == 49) ? 1 : 0;
        }
        __syncthreads();

        if (sTerm) {
            // ---- terminal: recover u, then fused inverse-FFT stage 0 (s=1, p=gid) ----
            // Recover entering lambda: la = (la_new - tau*fh*(G-1)) / (1 - tau*G/2)
#pragma unroll
            for (int e = 0; e < EP; e++) {
                float fr = fmaf((float)gid, FRC, (float)(e * 65536) * FRC - 0.5f);
                float d0 = fr - om0; d0 *= d0;
                float d1 = fr - om1; d1 *= d1;
                float d2 = fr - om2; d2 *= d2;
                float g0 = 1.0f / (1.0f + C_ALPHA * ((d0 + C_TAU2) + d1));
                float g1 = 1.0f / (1.0f + C_ALPHA * (((d1 + C_TAU2) + d0) + d2));
                float g2 = 1.0f / (1.0f + C_ALPHA * ((d2 + C_TAU2) + d1));
                float G  = g0 + g1 + g2;
                float inv = 1.0f / (1.0f - 0.5f * C_TAU * G);
                float lox = (lax[e] - C_TAU * fhx[e] * (G - 1.0f)) * inv;
                float loy = (lay[e] - C_TAU * fhy[e] * (G - 1.0f)) * inv;
                lax[e] = fhx[e] - 0.5f * lox;   // nr
                lay[e] = fhy[e] - 0.5f * loy;   // ni
            }
            float th0 = (float)(2.0 * PI_D / (double)TN);
            float sn, cs;
            sincosf(th0 * (float)gid, &sn, &cs);
            float2 w = make_float2(cs, sn);
            int ob = gid << 4;
#pragma unroll
            for (int k = 0; k < 3; k++) {
                float ok0 = (k == 0) ? om0 : (k == 1) ? om1 : om2;
                float2 z[16];
#pragma unroll
                for (int e = 0; e < EP; e++) {
                    float fr = fmaf((float)gid, FRC, (float)(e * 65536) * FRC - 0.5f);
                    float d0 = fr - om0; d0 *= d0;
                    float d1 = fr - om1; d1 *= d1;
                    float d2 = fr - om2; d2 *= d2;
                    float dk = fr - ok0; dk *= dk;
                    float nb = (k == 0) ? d1 : (k == 1) ? (d0 + d2) : d1;
                    float gk = 1.0f / (1.0f + C_ALPHA * ((dk + C_TAU2) + nb));
                    z[e] = make_float2(lax[e] * gk, lay[e] * gk);
                }
                fft16<false>(z);
                float2* __restrict__ Y = g_Bb + (k << LOG2TN);
                float2 cur = w;
                Y[ob] = z[0];
#pragma unroll
                for (int r = 1; r < 16; r++) {
                    Y[ob + r] = cmul(z[r], cur);
                    cur = cmul(cur, w);
                }
            }
            break;
        }
        oD0 = om0; oD1 = om1; oD2 = om2;
        om0 = sOm[0]; om1 = sOm[1]; om2 = sOm[2];
        __syncthreads();
    }
}

// ---------------- launch ----------------
extern "C" void kernel_launch(void* const* d_in, const int* in_sizes, int n_in,
                              void* d_out, int out_size) {
    const float* x   = (const float*)d_in[0];
    const float* om0 = (const float*)d_in[1];
    float* out = (float*)d_out;

    init_kernel<<<1, 32>>>(om0);

    // forward FFT of (-1)^n x: fused stage0 + 4 radix-16 stages -> fhat in g_Bb
    fwd0_kernel<<<256, 256>>>(x);
    for (int i = 1; i < 5; i++) {
        float th0 = (float)(-2.0 * PI_D * (double)(1 << (4 * i)) / (double)TN);
        fft16_stage<true><<<256, 256>>>(i & 1, 4 * i, th0);
    }

    vmd_persist<<<NBP, NTP>>>();   // ends with inverse stage 0 -> g_Bb (3 batches)

    // inverse stages 1..3 (batch 3): B->A->B->A
    for (int i = 1; i < 4; i++) {
        float th0 = (float)(2.0 * PI_D * (double)(1 << (4 * i)) / (double)TN);
        fft16_stage<false><<<768, 256>>>(i & 1, 4 * i, th0);
    }
    // final stage fused with real output (reads g_A)
    inv_final_kernel<<<768, 256>>>(out);
}